// round 10
// baseline (speedup 1.0000x reference)
#include <cuda_runtime.h>
#include <cuda_fp16.h>
#include <math.h>

#define NTOK 4096
#define DMODEL 1024
#define DFF 512
#define NH 16
#define DH 64
#define SEQ 2048

// ---------------- scratch (device globals: alloc-free, capture-safe) -------
__device__ float  g_xn[NTOK * DMODEL];
__device__ __half g_xn_h[NTOK * DMODEL];
__device__ __half g_qkv[NTOK * 3 * DMODEL];
__device__ __half g_attn_h[NTOK * DMODEL];
__device__ float  g_x1[NTOK * DMODEL];
__device__ __half g_h_h[NTOK * DMODEL];
__device__ __half g_hf[NTOK * DFF];
__device__ __half g_Wqkv[3 * DMODEL * DMODEL];
__device__ __half g_WoT[DMODEL * DMODEL];
__device__ __half g_W1T[DFF * DMODEL];
__device__ __half g_W2T[DMODEL * DFF];
__device__ float  g_bqkv[3 * DMODEL];

// ---------------- PTX helpers ---------------------------------------------
__device__ __forceinline__ unsigned sptr(const void* p) {
    return (unsigned)__cvta_generic_to_shared(p);
}
__device__ __forceinline__ void ldsm4(unsigned* r, unsigned addr) {
    asm volatile("ldmatrix.sync.aligned.m8n8.x4.shared.b16 {%0,%1,%2,%3}, [%4];"
        : "=r"(r[0]), "=r"(r[1]), "=r"(r[2]), "=r"(r[3]) : "r"(addr));
}
__device__ __forceinline__ void ldsm4t(unsigned* r, unsigned addr) {
    asm volatile("ldmatrix.sync.aligned.m8n8.x4.trans.shared.b16 {%0,%1,%2,%3}, [%4];"
        : "=r"(r[0]), "=r"(r[1]), "=r"(r[2]), "=r"(r[3]) : "r"(addr));
}
__device__ __forceinline__ void mma16816(float* c, const unsigned* a, unsigned b0, unsigned b1) {
    asm volatile("mma.sync.aligned.m16n8k16.row.col.f32.f16.f16.f32 "
        "{%0,%1,%2,%3},{%4,%5,%6,%7},{%8,%9},{%0,%1,%2,%3};"
        : "+f"(c[0]), "+f"(c[1]), "+f"(c[2]), "+f"(c[3])
        : "r"(a[0]), "r"(a[1]), "r"(a[2]), "r"(a[3]), "r"(b0), "r"(b1));
}
__device__ __forceinline__ void cpa16(unsigned dst, const void* src) {
    asm volatile("cp.async.cg.shared.global [%0], [%1], 16;" :: "r"(dst), "l"(src));
}
__device__ __forceinline__ void cp_commit() { asm volatile("cp.async.commit_group;"); }
__device__ __forceinline__ void cp_wait0()  { asm volatile("cp.async.wait_group 0;"); }

// ---------------- fused weight prep: transpose + fp32->half + bias --------
__global__ void prep_weights(const float* __restrict__ Wq, const float* __restrict__ Wk,
                             const float* __restrict__ Wv, const float* __restrict__ Wo,
                             const float* __restrict__ W1, const float* __restrict__ W2,
                             const float* __restrict__ bq, const float* __restrict__ bk,
                             const float* __restrict__ bv,
                             __half* __restrict__ Wqkv, __half* __restrict__ WoT,
                             __half* __restrict__ W1T, __half* __restrict__ W2T,
                             float* __restrict__ bqkv) {
    int id = blockIdx.x;
    int tx = threadIdx.x, ty = threadIdx.y;
    if (id >= 5120) {
        int w = id - 5120;
        const float* s = (w == 0) ? bq : (w == 1) ? bk : bv;
        int i = ty * 32 + tx;
#pragma unroll
        for (int j = 0; j < 4; j++) bqkv[w * 1024 + i + j * 256] = s[i + j * 256];
        return;
    }
    const float* src; __half* dst; int K, N, tile;
    if (id < 3072) {
        int w = id >> 10; tile = id & 1023;
        src = (w == 0) ? Wq : (w == 1) ? Wk : Wv;
        dst = Wqkv + (size_t)w * 1024 * 1024; K = 1024; N = 1024;
    } else if (id < 4096) { tile = id - 3072; src = Wo; dst = WoT; K = 1024; N = 1024; }
    else if (id < 4608)   { tile = id - 4096; src = W1; dst = W1T; K = 1024; N = 512; }
    else                  { tile = id - 4608; src = W2; dst = W2T; K = 512;  N = 1024; }
    int ntx = N >> 5;
    int k0 = (tile / ntx) * 32, n0 = (tile % ntx) * 32;
    __shared__ float t2[32][33];
#pragma unroll
    for (int i = 0; i < 4; i++)
        t2[ty + i * 8][tx] = src[(size_t)(k0 + ty + i * 8) * N + n0 + tx];
    __syncthreads();
#pragma unroll
    for (int i = 0; i < 4; i++)
        dst[(size_t)(n0 + ty + i * 8) * K + k0 + tx] = __float2half_rn(t2[tx][ty + i * 8]);
}

// ---------------- LayerNorm (unbiased var), fp32 + half outputs -----------
__global__ void ln_kernel(const float* __restrict__ x,
                          const float* __restrict__ alpha,
                          const float* __restrict__ beta,
                          float* __restrict__ y, __half* __restrict__ yh) {
    int row = blockIdx.x;
    int t = threadIdx.x;
    const float4* xr = (const float4*)(x + (size_t)row * DMODEL);
    float4 v = xr[t];
    float s  = v.x + v.y + v.z + v.w;
    float ss = v.x * v.x + v.y * v.y + v.z * v.z + v.w * v.w;
    __shared__ float sbuf[8], sbuf2[8];
#pragma unroll
    for (int m = 16; m; m >>= 1) {
        s  += __shfl_xor_sync(0xffffffffu, s, m);
        ss += __shfl_xor_sync(0xffffffffu, ss, m);
    }
    if ((t & 31) == 0) { sbuf[t >> 5] = s; sbuf2[t >> 5] = ss; }
    __syncthreads();
    if (t < 32) {
        s  = (t < 8) ? sbuf[t]  : 0.0f;
        ss = (t < 8) ? sbuf2[t] : 0.0f;
#pragma unroll
        for (int m = 4; m; m >>= 1) {
            s  += __shfl_xor_sync(0xffffffffu, s, m);
            ss += __shfl_xor_sync(0xffffffffu, ss, m);
        }
        if (t == 0) { sbuf[0] = s; sbuf2[0] = ss; }
    }
    __syncthreads();
    s = sbuf[0]; ss = sbuf2[0];
    float mean = s * (1.0f / DMODEL);
    float var  = (ss - (float)DMODEL * mean * mean) * (1.0f / (DMODEL - 1));
    float rstd = rsqrtf(var + 1e-6f);
    float4 a = ((const float4*)alpha)[t];
    float4 b = ((const float4*)beta)[t];
    float4 o;
    o.x = a.x * (v.x - mean) * rstd + b.x;
    o.y = a.y * (v.y - mean) * rstd + b.y;
    o.z = a.z * (v.z - mean) * rstd + b.z;
    o.w = a.w * (v.w - mean) * rstd + b.w;
    if (y) ((float4*)(y + (size_t)row * DMODEL))[t] = o;
    if (yh) {
        __half* p = yh + (size_t)row * DMODEL + t * 4;
        *(__half2*)(p)     = __floats2half2_rn(o.x, o.y);
        *(__half2*)(p + 2) = __floats2half2_rn(o.z, o.w);
    }
}

// ---------------- tensor-core GEMM, cp.async 2-stage pipeline -------------
#define GP 40
__global__ __launch_bounds__(256) void hgemm(
    const __half* __restrict__ A, const __half* __restrict__ B,
    const float* __restrict__ bias, const float* __restrict__ res,
    float* __restrict__ Cf, __half* __restrict__ Ch,
    int M, int N, int K, int relu) {
    __shared__ __half As[2][128 * GP];
    __shared__ __half Bs[2][128 * GP];
    int t = threadIdx.x, lane = t & 31, warp = t >> 5;
    int wy = warp >> 2, wx = warp & 3;
    int bm = blockIdx.y * 128, bn = blockIdx.x * 128;

    float acc[4][4][4];
#pragma unroll
    for (int i = 0; i < 4; i++)
#pragma unroll
        for (int j = 0; j < 4; j++)
#pragma unroll
            for (int c = 0; c < 4; c++) acc[i][j][c] = 0.0f;

    const __half* Ag = A + (size_t)(bm + (t >> 1)) * K + (t & 1) * 16;
    const __half* Bg = B + (size_t)(bn + (t >> 1)) * K + (t & 1) * 16;
    unsigned ldoff = ((t >> 1) * GP + (t & 1) * 16) * 2;
    unsigned asb[2] = {sptr(As[0]), sptr(As[1])};
    unsigned bsb[2] = {sptr(Bs[0]), sptr(Bs[1])};

    int arow = ((lane >> 3) & 1) * 8 + (lane & 7);
    int acol = (lane >> 4) * 8;
    int brow = (lane >> 4) * 8 + (lane & 7);
    int bcol = ((lane >> 3) & 1) * 8;

    {
        cpa16(asb[0] + ldoff, Ag);      cpa16(asb[0] + ldoff + 16, Ag + 8);
        cpa16(bsb[0] + ldoff, Bg);      cpa16(bsb[0] + ldoff + 16, Bg + 8);
        cp_commit();
    }
    int nIter = K >> 5;
    for (int it = 0; it < nIter; it++) {
        cp_wait0();
        __syncthreads();
        if (it + 1 < nIter) {
            int st = (it + 1) & 1, k0 = (it + 1) << 5;
            cpa16(asb[st] + ldoff, Ag + k0);      cpa16(asb[st] + ldoff + 16, Ag + k0 + 8);
            cpa16(bsb[st] + ldoff, Bg + k0);      cpa16(bsb[st] + ldoff + 16, Bg + k0 + 8);
            cp_commit();
        }
        unsigned as_u = asb[it & 1], bs_u = bsb[it & 1];
#pragma unroll
        for (int ks = 0; ks < 2; ks++) {
            unsigned af[4][4], bf[2][4];
#pragma unroll
            for (int mi = 0; mi < 4; mi++)
                ldsm4(af[mi], as_u + 2u * ((wy * 64 + mi * 16 + arow) * GP + ks * 16 + acol));
#pragma unroll
            for (int g = 0; g < 2; g++)
                ldsm4(bf[g], bs_u + 2u * ((wx * 32 + g * 16 + brow) * GP + ks * 16 + bcol));
#pragma unroll
            for (int mi = 0; mi < 4; mi++)
#pragma unroll
                for (int ni = 0; ni < 4; ni++)
                    mma16816(acc[mi][ni], af[mi], bf[ni >> 1][(ni & 1) * 2], bf[ni >> 1][(ni & 1) * 2 + 1]);
        }
    }

#pragma unroll
    for (int mi = 0; mi < 4; mi++) {
        int r = bm + wy * 64 + mi * 16 + (lane >> 2);
#pragma unroll
        for (int ni = 0; ni < 4; ni++) {
            int c = bn + wx * 32 + ni * 8 + 2 * (lane & 3);
            float* a = acc[mi][ni];
            float2 bb = *(const float2*)(bias + c);
            float v0 = a[0] + bb.x, v1 = a[1] + bb.y;
            float v2 = a[2] + bb.x, v3 = a[3] + bb.y;
            if (res) {
                float2 r0 = *(const float2*)(res + (size_t)r * N + c);
                float2 r1 = *(const float2*)(res + (size_t)(r + 8) * N + c);
                v0 += r0.x; v1 += r0.y; v2 += r1.x; v3 += r1.y;
            }
            if (relu) {
                v0 = fmaxf(v0, 0.0f); v1 = fmaxf(v1, 0.0f);
                v2 = fmaxf(v2, 0.0f); v3 = fmaxf(v3, 0.0f);
            }
            if (Cf) {
                *(float2*)(Cf + (size_t)r * N + c)       = make_float2(v0, v1);
                *(float2*)(Cf + (size_t)(r + 8) * N + c) = make_float2(v2, v3);
            }
            if (Ch) {
                *(__half2*)(Ch + (size_t)r * N + c)       = __floats2half2_rn(v0, v1);
                *(__half2*)(Ch + (size_t)(r + 8) * N + c) = __floats2half2_rn(v2, v3);
            }
        }
    }
}

// ---------------- flash attention: 256 thr / 128 q-rows, exp2 domain ------
// launch_bounds(256,3): cap regs ~85 so 3 CTAs fit per SM (was 2 @ 98 regs).
#define AP 72
#define QSCALE 0.18033688011112042f   // log2(e)/8
__global__ __launch_bounds__(256, 3) void attn(const __half* __restrict__ qkv,
                                               __half* __restrict__ o) {
    __shared__ __half smA[128 * AP];   // Q staging, then K/V stage 1
    __shared__ __half smB[128 * AP];   // K/V stage 0
    int t = threadIdx.x, lane = t & 31, warp = t >> 5;
    int qt = blockIdx.x, h = blockIdx.y, b = blockIdx.z;
    size_t tq0 = (size_t)b * SEQ + qt * 128;
    const __half* Qg = qkv + tq0 * 3072 + h * 64;
    const __half* Kg = qkv + ((size_t)b * SEQ) * 3072 + 1024 + h * 64;
    const __half* Vg = Kg + 1024;

    unsigned ksu[2] = {sptr(smB), sptr(smA)};
    unsigned vsu[2] = {sptr(smB + 64 * AP), sptr(smA + 64 * AP)};

    int ldrow = t >> 2, ldo = (t & 3) * 16;
    unsigned kvoff = (ldrow * AP + ldo) * 2;

    // prologue: K/V tile 0 -> stage 0 (region B); overlaps Q staging
    {
        size_t tb = (size_t)ldrow * 3072;
        cpa16(ksu[0] + kvoff, Kg + tb + ldo);      cpa16(ksu[0] + kvoff + 16, Kg + tb + ldo + 8);
        cpa16(vsu[0] + kvoff, Vg + tb + ldo);      cpa16(vsu[0] + kvoff + 16, Vg + tb + ldo + 8);
        cp_commit();
    }

    // stage Q (128 x 64 halves) into region A, pre-scaled by log2(e)/8
    {
        int row = t >> 1;
        const __half* src = Qg + (size_t)row * 3072 + (t & 1) * 32;
        __half* dst = smA + row * AP + (t & 1) * 32;
        __half2 qs = __float2half2_rn(QSCALE);
#pragma unroll
        for (int i = 0; i < 16; i++) {
            __half2 qv = *(const __half2*)(src + i * 2);
            *(__half2*)(dst + i * 2) = __hmul2(qv, qs);
        }
    }
    __syncthreads();

    int arow = ((lane >> 3) & 1) * 8 + (lane & 7);
    int acol = (lane >> 4) * 8;
    unsigned smA_u = sptr(smA);
    unsigned qf[4][4];
#pragma unroll
    for (int ks = 0; ks < 4; ks++)
        ldsm4(qf[ks], smA_u + 2u * ((warp * 16 + arow) * AP + ks * 16 + acol));

    float m0 = -1e30f, m1 = -1e30f, l0 = 0.0f, l1 = 0.0f;
    float O[8][4];
#pragma unroll
    for (int j = 0; j < 8; j++)
#pragma unroll
        for (int c = 0; c < 4; c++) O[j][c] = 0.0f;

    int krow = (lane >> 4) * 8 + (lane & 7);
    int kcol = ((lane >> 3) & 1) * 8;
    int vrow = ((lane >> 3) & 1) * 8 + (lane & 7);
    int vcol = (lane >> 4) * 8;

    for (int kt = 0; kt < 32; kt++) {
        cp_wait0();
        __syncthreads();
        if (kt + 1 < 32) {
            int st = (kt + 1) & 1;
            size_t tb = (size_t)((kt + 1) * 64 + ldrow) * 3072;
            cpa16(ksu[st] + kvoff, Kg + tb + ldo);      cpa16(ksu[st] + kvoff + 16, Kg + tb + ldo + 8);
            cpa16(vsu[st] + kvoff, Vg + tb + ldo);      cpa16(vsu[st] + kvoff + 16, Vg + tb + ldo + 8);
            cp_commit();
        }
        unsigned ks_u = ksu[kt & 1], vs_u = vsu[kt & 1];

        // S = Qs @ K^T (log2 domain)
        float s[8][4];
#pragma unroll
        for (int j = 0; j < 8; j++)
#pragma unroll
            for (int c = 0; c < 4; c++) s[j][c] = 0.0f;
#pragma unroll
        for (int ks = 0; ks < 4; ks++) {
            unsigned kf[4][4];
#pragma unroll
            for (int g = 0; g < 4; g++)
                ldsm4(kf[g], ks_u + 2u * ((g * 16 + krow) * AP + ks * 16 + kcol));
#pragma unroll
            for (int j = 0; j < 8; j++)
                mma16816(s[j], qf[ks], kf[j >> 1][(j & 1) * 2], kf[j >> 1][(j & 1) * 2 + 1]);
        }

        // online softmax (exp2 domain)
        float mx0 = -1e30f, mx1 = -1e30f;
#pragma unroll
        for (int j = 0; j < 8; j++) {
            mx0 = fmaxf(mx0, fmaxf(s[j][0], s[j][1]));
            mx1 = fmaxf(mx1, fmaxf(s[j][2], s[j][3]));
        }
        mx0 = fmaxf(mx0, __shfl_xor_sync(0xffffffffu, mx0, 1));
        mx0 = fmaxf(mx0, __shfl_xor_sync(0xffffffffu, mx0, 2));
        mx1 = fmaxf(mx1, __shfl_xor_sync(0xffffffffu, mx1, 1));
        mx1 = fmaxf(mx1, __shfl_xor_sync(0xffffffffu, mx1, 2));
        bool up0 = mx0 > m0, up1 = mx1 > m1;
        float mn0 = up0 ? mx0 : m0, mn1 = up1 ? mx1 : m1;
        if (up0 | up1) {
            float al0 = up0 ? exp2f(m0 - mn0) : 1.0f;
            float al1 = up1 ? exp2f(m1 - mn1) : 1.0f;
            m0 = mn0; m1 = mn1;
            l0 *= al0; l1 *= al1;
#pragma unroll
            for (int j = 0; j < 8; j++) {
                O[j][0] *= al0; O[j][1] *= al0;
                O[j][2] *= al1; O[j][3] *= al1;
            }
        }
        float sum0 = 0.0f, sum1 = 0.0f;
        unsigned pa[8], pb[8];
#pragma unroll
        for (int j = 0; j < 8; j++) {
            s[j][0] = exp2f(s[j][0] - mn0); s[j][1] = exp2f(s[j][1] - mn0);
            s[j][2] = exp2f(s[j][2] - mn1); s[j][3] = exp2f(s[j][3] - mn1);
            sum0 += s[j][0] + s[j][1];
            sum1 += s[j][2] + s[j][3];
            __half2 h0 = __floats2half2_rn(s[j][0], s[j][1]);
            __half2 h1 = __floats2half2_rn(s[j][2], s[j][3]);
            pa[j] = *(unsigned*)&h0;
            pb[j] = *(unsigned*)&h1;
        }
        sum0 += __shfl_xor_sync(0xffffffffu, sum0, 1);
        sum0 += __shfl_xor_sync(0xffffffffu, sum0, 2);
        sum1 += __shfl_xor_sync(0xffffffffu, sum1, 1);
        sum1 += __shfl_xor_sync(0xffffffffu, sum1, 2);
        l0 += sum0;
        l1 += sum1;

        // O += P @ V
#pragma unroll
        for (int ks = 0; ks < 4; ks++) {
            unsigned vf[4][4];
#pragma unroll
            for (int g = 0; g < 4; g++)
                ldsm4t(vf[g], vs_u + 2u * ((ks * 16 + vrow) * AP + g * 16 + vcol));
            unsigned pfr[4] = {pa[2 * ks], pb[2 * ks], pa[2 * ks + 1], pb[2 * ks + 1]};
#pragma unroll
            for (int j = 0; j < 8; j++)
                mma16816(O[j], pfr, vf[j >> 1][(j & 1) * 2], vf[j >> 1][(j & 1) * 2 + 1]);
        }
    }

    float i0 = 1.0f / l0, i1 = 1.0f / l1;
    __half* ob = o + (tq0 + warp * 16 + (lane >> 2)) * 1024 + h * 64 + 2 * (lane & 3);
#pragma unroll
    for (int j = 0; j < 8; j++) {
        *(__half2*)(ob + j * 8)            = __floats2half2_rn(O[j][0] * i0, O[j][1] * i0);
        *(__half2*)(ob + 8 * 1024 + j * 8) = __floats2half2_rn(O[j][2] * i1, O[j][3] * i1);
    }
}

// ---------------------------------------------------------------------------
extern "C" void kernel_launch(void* const* d_in, const int* in_sizes, int n_in,
                              void* d_out, int out_size) {
    const float* x      = (const float*)d_in[0];
    const float* Wq     = (const float*)d_in[1];
    const float* bq     = (const float*)d_in[2];
    const float* Wk     = (const float*)d_in[3];
    const float* bk     = (const float*)d_in[4];
    const float* Wv     = (const float*)d_in[5];
    const float* bv     = (const float*)d_in[6];
    const float* Wo     = (const float*)d_in[7];
    const float* bo     = (const float*)d_in[8];
    const float* alpha1 = (const float*)d_in[9];
    const float* beta1  = (const float*)d_in[10];
    const float* alpha2 = (const float*)d_in[11];
    const float* beta2  = (const float*)d_in[12];
    const float* W1     = (const float*)d_in[13];
    const float* b1     = (const float*)d_in[14];
    const float* W2     = (const float*)d_in[15];
    const float* b2     = (const float*)d_in[16];
    float* out = (float*)d_out;

    float *p_xn, *p_x1, *p_bqkv;
    __half *p_xn_h, *p_qkv, *p_attn_h, *p_h_h, *p_hf;
    __half *p_Wqkv, *p_WoT, *p_W1T, *p_W2T;
    cudaGetSymbolAddress((void**)&p_xn,     g_xn);
    cudaGetSymbolAddress((void**)&p_xn_h,   g_xn_h);
    cudaGetSymbolAddress((void**)&p_qkv,    g_qkv);
    cudaGetSymbolAddress((void**)&p_attn_h, g_attn_h);
    cudaGetSymbolAddress((void**)&p_x1,     g_x1);
    cudaGetSymbolAddress((void**)&p_h_h,    g_h_h);
    cudaGetSymbolAddress((void**)&p_hf,     g_hf);
    cudaGetSymbolAddress((void**)&p_Wqkv,   g_Wqkv);
    cudaGetSymbolAddress((void**)&p_WoT,    g_WoT);
    cudaGetSymbolAddress((void**)&p_W1T,    g_W1T);
    cudaGetSymbolAddress((void**)&p_W2T,    g_W2T);
    cudaGetSymbolAddress((void**)&p_bqkv,   g_bqkv);

    prep_weights<<<5123, dim3(32, 8)>>>(Wq, Wk, Wv, Wo, W1, W2, bq, bk, bv,
                                        p_Wqkv, p_WoT, p_W1T, p_W2T, p_bqkv);
    ln_kernel<<<NTOK, 256>>>(x, alpha1, beta1, p_xn, p_xn_h);
    hgemm<<<dim3(24, 32), 256>>>(p_xn_h, p_Wqkv, p_bqkv, nullptr,
                                 nullptr, p_qkv, NTOK, 3072, 1024, 0);
    attn<<<dim3(SEQ / 128, NH, 2), 256>>>(p_qkv, p_attn_h);
    hgemm<<<dim3(8, 32), 256>>>(p_attn_h, p_WoT, bo, p_xn,
                                p_x1, nullptr, NTOK, 1024, 1024, 0);
    ln_kernel<<<NTOK, 256>>>(p_x1, alpha2, beta2, nullptr, p_h_h);
    hgemm<<<dim3(4, 32), 256>>>(p_h_h, p_W1T, b1, nullptr,
                                nullptr, p_hf, NTOK, 512, 1024, 1);
    hgemm<<<dim3(8, 32), 256>>>(p_hf, p_W2T, b2, p_x1,
                                out, nullptr, NTOK, 1024, 512, 0);
}

// round 12
// speedup vs baseline: 1.0592x; 1.0592x over previous
#include <cuda_runtime.h>
#include <cuda_fp16.h>
#include <math.h>

#define NTOK 4096
#define DMODEL 1024
#define DFF 512
#define NH 16
#define DH 64
#define SEQ 2048

// ---------------- scratch (device globals: alloc-free, capture-safe) -------
__device__ float  g_xn[NTOK * DMODEL];
__device__ __half g_xn_h[NTOK * DMODEL];
__device__ __half g_qkv[NTOK * 3 * DMODEL];
__device__ __half g_attn_h[NTOK * DMODEL];
__device__ float  g_x1[NTOK * DMODEL];
__device__ __half g_h_h[NTOK * DMODEL];
__device__ __half g_hf[NTOK * DFF];
__device__ __half g_Wqkv[3 * DMODEL * DMODEL];
__device__ __half g_WoT[DMODEL * DMODEL];
__device__ __half g_W1T[DFF * DMODEL];
__device__ __half g_W2T[DMODEL * DFF];
__device__ float  g_bqkv[3 * DMODEL];

// ---------------- PTX helpers ---------------------------------------------
__device__ __forceinline__ unsigned sptr(const void* p) {
    return (unsigned)__cvta_generic_to_shared(p);
}
__device__ __forceinline__ void ldsm4(unsigned* r, unsigned addr) {
    asm volatile("ldmatrix.sync.aligned.m8n8.x4.shared.b16 {%0,%1,%2,%3}, [%4];"
        : "=r"(r[0]), "=r"(r[1]), "=r"(r[2]), "=r"(r[3]) : "r"(addr));
}
__device__ __forceinline__ void ldsm4t(unsigned* r, unsigned addr) {
    asm volatile("ldmatrix.sync.aligned.m8n8.x4.trans.shared.b16 {%0,%1,%2,%3}, [%4];"
        : "=r"(r[0]), "=r"(r[1]), "=r"(r[2]), "=r"(r[3]) : "r"(addr));
}
__device__ __forceinline__ void mma16816(float* c, const unsigned* a, unsigned b0, unsigned b1) {
    asm volatile("mma.sync.aligned.m16n8k16.row.col.f32.f16.f16.f32 "
        "{%0,%1,%2,%3},{%4,%5,%6,%7},{%8,%9},{%0,%1,%2,%3};"
        : "+f"(c[0]), "+f"(c[1]), "+f"(c[2]), "+f"(c[3])
        : "r"(a[0]), "r"(a[1]), "r"(a[2]), "r"(a[3]), "r"(b0), "r"(b1));
}
__device__ __forceinline__ void cpa16(unsigned dst, const void* src) {
    asm volatile("cp.async.cg.shared.global [%0], [%1], 16;" :: "r"(dst), "l"(src));
}
__device__ __forceinline__ void cp_commit() { asm volatile("cp.async.commit_group;"); }
__device__ __forceinline__ void cp_wait0()  { asm volatile("cp.async.wait_group 0;"); }
__device__ __forceinline__ void cp_wait1()  { asm volatile("cp.async.wait_group 1;"); }

// ---------------- fused weight prep: transpose + fp32->half + bias --------
__global__ void prep_weights(const float* __restrict__ Wq, const float* __restrict__ Wk,
                             const float* __restrict__ Wv, const float* __restrict__ Wo,
                             const float* __restrict__ W1, const float* __restrict__ W2,
                             const float* __restrict__ bq, const float* __restrict__ bk,
                             const float* __restrict__ bv,
                             __half* __restrict__ Wqkv, __half* __restrict__ WoT,
                             __half* __restrict__ W1T, __half* __restrict__ W2T,
                             float* __restrict__ bqkv) {
    int id = blockIdx.x;
    int tx = threadIdx.x, ty = threadIdx.y;
    if (id >= 5120) {
        int w = id - 5120;
        const float* s = (w == 0) ? bq : (w == 1) ? bk : bv;
        int i = ty * 32 + tx;
#pragma unroll
        for (int j = 0; j < 4; j++) bqkv[w * 1024 + i + j * 256] = s[i + j * 256];
        return;
    }
    const float* src; __half* dst; int K, N, tile;
    if (id < 3072) {
        int w = id >> 10; tile = id & 1023;
        src = (w == 0) ? Wq : (w == 1) ? Wk : Wv;
        dst = Wqkv + (size_t)w * 1024 * 1024; K = 1024; N = 1024;
    } else if (id < 4096) { tile = id - 3072; src = Wo; dst = WoT; K = 1024; N = 1024; }
    else if (id < 4608)   { tile = id - 4096; src = W1; dst = W1T; K = 1024; N = 512; }
    else                  { tile = id - 4608; src = W2; dst = W2T; K = 512;  N = 1024; }
    int ntx = N >> 5;
    int k0 = (tile / ntx) * 32, n0 = (tile % ntx) * 32;
    __shared__ float t2[32][33];
#pragma unroll
    for (int i = 0; i < 4; i++)
        t2[ty + i * 8][tx] = src[(size_t)(k0 + ty + i * 8) * N + n0 + tx];
    __syncthreads();
#pragma unroll
    for (int i = 0; i < 4; i++)
        dst[(size_t)(n0 + ty + i * 8) * K + k0 + tx] = __float2half_rn(t2[tx][ty + i * 8]);
}

// ---------------- LayerNorm (unbiased var), fp32 + half outputs -----------
__global__ void ln_kernel(const float* __restrict__ x,
                          const float* __restrict__ alpha,
                          const float* __restrict__ beta,
                          float* __restrict__ y, __half* __restrict__ yh) {
    int row = blockIdx.x;
    int t = threadIdx.x;
    const float4* xr = (const float4*)(x + (size_t)row * DMODEL);
    float4 v = xr[t];
    float s  = v.x + v.y + v.z + v.w;
    float ss = v.x * v.x + v.y * v.y + v.z * v.z + v.w * v.w;
    __shared__ float sbuf[8], sbuf2[8];
#pragma unroll
    for (int m = 16; m; m >>= 1) {
        s  += __shfl_xor_sync(0xffffffffu, s, m);
        ss += __shfl_xor_sync(0xffffffffu, ss, m);
    }
    if ((t & 31) == 0) { sbuf[t >> 5] = s; sbuf2[t >> 5] = ss; }
    __syncthreads();
    if (t < 32) {
        s  = (t < 8) ? sbuf[t]  : 0.0f;
        ss = (t < 8) ? sbuf2[t] : 0.0f;
#pragma unroll
        for (int m = 4; m; m >>= 1) {
            s  += __shfl_xor_sync(0xffffffffu, s, m);
            ss += __shfl_xor_sync(0xffffffffu, ss, m);
        }
        if (t == 0) { sbuf[0] = s; sbuf2[0] = ss; }
    }
    __syncthreads();
    s = sbuf[0]; ss = sbuf2[0];
    float mean = s * (1.0f / DMODEL);
    float var  = (ss - (float)DMODEL * mean * mean) * (1.0f / (DMODEL - 1));
    float rstd = rsqrtf(var + 1e-6f);
    float4 a = ((const float4*)alpha)[t];
    float4 b = ((const float4*)beta)[t];
    float4 o;
    o.x = a.x * (v.x - mean) * rstd + b.x;
    o.y = a.y * (v.y - mean) * rstd + b.y;
    o.z = a.z * (v.z - mean) * rstd + b.z;
    o.w = a.w * (v.w - mean) * rstd + b.w;
    if (y) ((float4*)(y + (size_t)row * DMODEL))[t] = o;
    if (yh) {
        __half* p = yh + (size_t)row * DMODEL + t * 4;
        *(__half2*)(p)     = __floats2half2_rn(o.x, o.y);
        *(__half2*)(p + 2) = __floats2half2_rn(o.z, o.w);
    }
}

// ---------------- tensor-core GEMM, cp.async 3-stage pipeline -------------
#define GP 40
__global__ __launch_bounds__(256) void hgemm(
    const __half* __restrict__ A, const __half* __restrict__ B,
    const float* __restrict__ bias, const float* __restrict__ res,
    float* __restrict__ Cf, __half* __restrict__ Ch,
    int M, int N, int K, int relu) {
    __shared__ __half As[3][128 * GP];
    __shared__ __half Bs[3][128 * GP];
    int t = threadIdx.x, lane = t & 31, warp = t >> 5;
    int wy = warp >> 2, wx = warp & 3;
    int bm = blockIdx.y * 128, bn = blockIdx.x * 128;

    float acc[4][4][4];
#pragma unroll
    for (int i = 0; i < 4; i++)
#pragma unroll
        for (int j = 0; j < 4; j++)
#pragma unroll
            for (int c = 0; c < 4; c++) acc[i][j][c] = 0.0f;

    const __half* Ag = A + (size_t)(bm + (t >> 1)) * K + (t & 1) * 16;
    const __half* Bg = B + (size_t)(bn + (t >> 1)) * K + (t & 1) * 16;
    unsigned ldoff = ((t >> 1) * GP + (t & 1) * 16) * 2;
    unsigned asb[3] = {sptr(As[0]), sptr(As[1]), sptr(As[2])};
    unsigned bsb[3] = {sptr(Bs[0]), sptr(Bs[1]), sptr(Bs[2])};

    int arow = ((lane >> 3) & 1) * 8 + (lane & 7);
    int acol = (lane >> 4) * 8;
    int brow = (lane >> 4) * 8 + (lane & 7);
    int bcol = ((lane >> 3) & 1) * 8;

    int nIter = K >> 5;
    // prologue: stages 0,1 (nIter >= 16 for all our shapes)
#pragma unroll
    for (int st = 0; st < 2; st++) {
        int k0 = st << 5;
        cpa16(asb[st] + ldoff, Ag + k0);      cpa16(asb[st] + ldoff + 16, Ag + k0 + 8);
        cpa16(bsb[st] + ldoff, Bg + k0);      cpa16(bsb[st] + ldoff + 16, Bg + k0 + 8);
        cp_commit();
    }
    for (int it = 0; it < nIter; it++) {
        if (it + 1 < nIter) cp_wait1(); else cp_wait0();
        __syncthreads();
        if (it + 2 < nIter) {
            int st = (it + 2) % 3, k0 = (it + 2) << 5;
            cpa16(asb[st] + ldoff, Ag + k0);      cpa16(asb[st] + ldoff + 16, Ag + k0 + 8);
            cpa16(bsb[st] + ldoff, Bg + k0);      cpa16(bsb[st] + ldoff + 16, Bg + k0 + 8);
            cp_commit();
        }
        int cur = it % 3;
        unsigned as_u = asb[cur], bs_u = bsb[cur];
#pragma unroll
        for (int ks = 0; ks < 2; ks++) {
            unsigned af[4][4], bf[2][4];
#pragma unroll
            for (int mi = 0; mi < 4; mi++)
                ldsm4(af[mi], as_u + 2u * ((wy * 64 + mi * 16 + arow) * GP + ks * 16 + acol));
#pragma unroll
            for (int g = 0; g < 2; g++)
                ldsm4(bf[g], bs_u + 2u * ((wx * 32 + g * 16 + brow) * GP + ks * 16 + bcol));
#pragma unroll
            for (int mi = 0; mi < 4; mi++)
#pragma unroll
                for (int ni = 0; ni < 4; ni++)
                    mma16816(acc[mi][ni], af[mi], bf[ni >> 1][(ni & 1) * 2], bf[ni >> 1][(ni & 1) * 2 + 1]);
        }
    }

#pragma unroll
    for (int mi = 0; mi < 4; mi++) {
        int r = bm + wy * 64 + mi * 16 + (lane >> 2);
#pragma unroll
        for (int ni = 0; ni < 4; ni++) {
            int c = bn + wx * 32 + ni * 8 + 2 * (lane & 3);
            float* a = acc[mi][ni];
            float2 bb = *(const float2*)(bias + c);
            float v0 = a[0] + bb.x, v1 = a[1] + bb.y;
            float v2 = a[2] + bb.x, v3 = a[3] + bb.y;
            if (res) {
                float2 r0 = *(const float2*)(res + (size_t)r * N + c);
                float2 r1 = *(const float2*)(res + (size_t)(r + 8) * N + c);
                v0 += r0.x; v1 += r0.y; v2 += r1.x; v3 += r1.y;
            }
            if (relu) {
                v0 = fmaxf(v0, 0.0f); v1 = fmaxf(v1, 0.0f);
                v2 = fmaxf(v2, 0.0f); v3 = fmaxf(v3, 0.0f);
            }
            if (Cf) {
                *(float2*)(Cf + (size_t)r * N + c)       = make_float2(v0, v1);
                *(float2*)(Cf + (size_t)(r + 8) * N + c) = make_float2(v2, v3);
            }
            if (Ch) {
                *(__half2*)(Ch + (size_t)r * N + c)       = __floats2half2_rn(v0, v1);
                *(__half2*)(Ch + (size_t)(r + 8) * N + c) = __floats2half2_rn(v2, v3);
            }
        }
    }
}

// ---------------- flash attention: R4 shape + exp2 + split-half overlap ---
// 256 thr / 128 q-rows / natural regs.  Per 64-token tile, softmax+PV run in
// two 32-token halves so PV-mma(half A) overlaps softmax(half B).
#define AP 72
#define QSCALE 0.18033688011112042f   // log2(e)/8
__global__ __launch_bounds__(256) void attn(const __half* __restrict__ qkv,
                                            __half* __restrict__ o) {
    __shared__ __half smA[128 * AP];   // Q staging, then K/V stage 1
    __shared__ __half smB[128 * AP];   // K/V stage 0
    int t = threadIdx.x, lane = t & 31, warp = t >> 5;
    int qt = blockIdx.x, h = blockIdx.y, b = blockIdx.z;
    size_t tq0 = (size_t)b * SEQ + qt * 128;
    const __half* Qg = qkv + tq0 * 3072 + h * 64;
    const __half* Kg = qkv + ((size_t)b * SEQ) * 3072 + 1024 + h * 64;
    const __half* Vg = Kg + 1024;

    unsigned ksu[2] = {sptr(smB), sptr(smA)};
    unsigned vsu[2] = {sptr(smB + 64 * AP), sptr(smA + 64 * AP)};

    int ldrow = t >> 2, ldo = (t & 3) * 16;
    unsigned kvoff = (ldrow * AP + ldo) * 2;

    // prologue: K/V tile 0 -> stage 0 (region B); overlaps Q staging
    {
        size_t tb = (size_t)ldrow * 3072;
        cpa16(ksu[0] + kvoff, Kg + tb + ldo);      cpa16(ksu[0] + kvoff + 16, Kg + tb + ldo + 8);
        cpa16(vsu[0] + kvoff, Vg + tb + ldo);      cpa16(vsu[0] + kvoff + 16, Vg + tb + ldo + 8);
        cp_commit();
    }

    // stage Q (128 x 64 halves) into region A, pre-scaled by log2(e)/8
    {
        int row = t >> 1;
        const __half* src = Qg + (size_t)row * 3072 + (t & 1) * 32;
        __half* dst = smA + row * AP + (t & 1) * 32;
        __half2 qs = __float2half2_rn(QSCALE);
#pragma unroll
        for (int i = 0; i < 16; i++) {
            __half2 qv = *(const __half2*)(src + i * 2);
            *(__half2*)(dst + i * 2) = __hmul2(qv, qs);
        }
    }
    __syncthreads();

    int arow = ((lane >> 3) & 1) * 8 + (lane & 7);
    int acol = (lane >> 4) * 8;
    unsigned smA_u = sptr(smA);
    unsigned qf[4][4];
#pragma unroll
    for (int ks = 0; ks < 4; ks++)
        ldsm4(qf[ks], smA_u + 2u * ((warp * 16 + arow) * AP + ks * 16 + acol));

    float m0 = -1e30f, m1 = -1e30f, l0 = 0.0f, l1 = 0.0f;
    float O[8][4];
#pragma unroll
    for (int j = 0; j < 8; j++)
#pragma unroll
        for (int c = 0; c < 4; c++) O[j][c] = 0.0f;

    int krow = (lane >> 4) * 8 + (lane & 7);
    int kcol = ((lane >> 3) & 1) * 8;
    int vrow = ((lane >> 3) & 1) * 8 + (lane & 7);
    int vcol = (lane >> 4) * 8;

    for (int kt = 0; kt < 32; kt++) {
        cp_wait0();
        __syncthreads();
        if (kt + 1 < 32) {
            int st = (kt + 1) & 1;
            size_t tb = (size_t)((kt + 1) * 64 + ldrow) * 3072;
            cpa16(ksu[st] + kvoff, Kg + tb + ldo);      cpa16(ksu[st] + kvoff + 16, Kg + tb + ldo + 8);
            cpa16(vsu[st] + kvoff, Vg + tb + ldo);      cpa16(vsu[st] + kvoff + 16, Vg + tb + ldo + 8);
            cp_commit();
        }
        unsigned ks_u = ksu[kt & 1], vs_u = vsu[kt & 1];

        // S = Qs @ K^T (log2 domain)
        float s[8][4];
#pragma unroll
        for (int j = 0; j < 8; j++)
#pragma unroll
            for (int c = 0; c < 4; c++) s[j][c] = 0.0f;
#pragma unroll
        for (int ks = 0; ks < 4; ks++) {
            unsigned kf[4][4];
#pragma unroll
            for (int g = 0; g < 4; g++)
                ldsm4(kf[g], ks_u + 2u * ((g * 16 + krow) * AP + ks * 16 + kcol));
#pragma unroll
            for (int j = 0; j < 8; j++)
                mma16816(s[j], qf[ks], kf[j >> 1][(j & 1) * 2], kf[j >> 1][(j & 1) * 2 + 1]);
        }

        // process two 32-token halves: softmax(half) then PV(half);
        // PV-mma of half 0 overlaps softmax scalar work of half 1 via ILP.
#pragma unroll
        for (int hh = 0; hh < 2; hh++) {
            int j0 = hh * 4;
            float mx0 = -1e30f, mx1 = -1e30f;
#pragma unroll
            for (int j = j0; j < j0 + 4; j++) {
                mx0 = fmaxf(mx0, fmaxf(s[j][0], s[j][1]));
                mx1 = fmaxf(mx1, fmaxf(s[j][2], s[j][3]));
            }
            mx0 = fmaxf(mx0, __shfl_xor_sync(0xffffffffu, mx0, 1));
            mx0 = fmaxf(mx0, __shfl_xor_sync(0xffffffffu, mx0, 2));
            mx1 = fmaxf(mx1, __shfl_xor_sync(0xffffffffu, mx1, 1));
            mx1 = fmaxf(mx1, __shfl_xor_sync(0xffffffffu, mx1, 2));
            bool up0 = mx0 > m0, up1 = mx1 > m1;
            float mn0 = up0 ? mx0 : m0, mn1 = up1 ? mx1 : m1;
            if (up0 | up1) {
                float al0 = up0 ? exp2f(m0 - mn0) : 1.0f;
                float al1 = up1 ? exp2f(m1 - mn1) : 1.0f;
                m0 = mn0; m1 = mn1;
                l0 *= al0; l1 *= al1;
#pragma unroll
                for (int j = 0; j < 8; j++) {
                    O[j][0] *= al0; O[j][1] *= al0;
                    O[j][2] *= al1; O[j][3] *= al1;
                }
            }
            float sum0 = 0.0f, sum1 = 0.0f;
            unsigned pa[4], pb[4];
#pragma unroll
            for (int j = j0; j < j0 + 4; j++) {
                float e0 = exp2f(s[j][0] - mn0), e1 = exp2f(s[j][1] - mn0);
                float e2 = exp2f(s[j][2] - mn1), e3 = exp2f(s[j][3] - mn1);
                sum0 += e0 + e1;
                sum1 += e2 + e3;
                __half2 h0 = __floats2half2_rn(e0, e1);
                __half2 h1 = __floats2half2_rn(e2, e3);
                pa[j - j0] = *(unsigned*)&h0;
                pb[j - j0] = *(unsigned*)&h1;
            }
            sum0 += __shfl_xor_sync(0xffffffffu, sum0, 1);
            sum0 += __shfl_xor_sync(0xffffffffu, sum0, 2);
            sum1 += __shfl_xor_sync(0xffffffffu, sum1, 1);
            sum1 += __shfl_xor_sync(0xffffffffu, sum1, 2);
            l0 += sum0;
            l1 += sum1;

            // O += P(half) @ V(rows hh*32 .. hh*32+31)
#pragma unroll
            for (int kk = 0; kk < 2; kk++) {
                int ks = hh * 2 + kk;
                unsigned vf[4][4];
#pragma unroll
                for (int g = 0; g < 4; g++)
                    ldsm4t(vf[g], vs_u + 2u * ((ks * 16 + vrow) * AP + g * 16 + vcol));
                unsigned pfr[4] = {pa[2 * kk], pb[2 * kk], pa[2 * kk + 1], pb[2 * kk + 1]};
#pragma unroll
                for (int j = 0; j < 8; j++)
                    mma16816(O[j], pfr, vf[j >> 1][(j & 1) * 2], vf[j >> 1][(j & 1) * 2 + 1]);
            }
        }
    }

    float i0 = 1.0f / l0, i1 = 1.0f / l1;
    __half* ob = o + (tq0 + warp * 16 + (lane >> 2)) * 1024 + h * 64 + 2 * (lane & 3);
#pragma unroll
    for (int j = 0; j < 8; j++) {
        *(__half2*)(ob + j * 8)            = __floats2half2_rn(O[j][0] * i0, O[j][1] * i0);
        *(__half2*)(ob + 8 * 1024 + j * 8) = __floats2half2_rn(O[j][2] * i1, O[j][3] * i1);
    }
}

// ---------------------------------------------------------------------------
extern "C" void kernel_launch(void* const* d_in, const int* in_sizes, int n_in,
                              void* d_out, int out_size) {
    const float* x      = (const float*)d_in[0];
    const float* Wq     = (const float*)d_in[1];
    const float* bq     = (const float*)d_in[2];
    const float* Wk     = (const float*)d_in[3];
    const float* bk     = (const float*)d_in[4];
    const float* Wv     = (const float*)d_in[5];
    const float* bv     = (const float*)d_in[6];
    const float* Wo     = (const float*)d_in[7];
    const float* bo     = (const float*)d_in[8];
    const float* alpha1 = (const float*)d_in[9];
    const float* beta1  = (const float*)d_in[10];
    const float* alpha2 = (const float*)d_in[11];
    const float* beta2  = (const float*)d_in[12];
    const float* W1     = (const float*)d_in[13];
    const float* b1     = (const float*)d_in[14];
    const float* W2     = (const float*)d_in[15];
    const float* b2     = (const float*)d_in[16];
    float* out = (float*)d_out;

    float *p_xn, *p_x1, *p_bqkv;
    __half *p_xn_h, *p_qkv, *p_attn_h, *p_h_h, *p_hf;
    __half *p_Wqkv, *p_WoT, *p_W1T, *p_W2T;
    cudaGetSymbolAddress((void**)&p_xn,     g_xn);
    cudaGetSymbolAddress((void**)&p_xn_h,   g_xn_h);
    cudaGetSymbolAddress((void**)&p_qkv,    g_qkv);
    cudaGetSymbolAddress((void**)&p_attn_h, g_attn_h);
    cudaGetSymbolAddress((void**)&p_x1,     g_x1);
    cudaGetSymbolAddress((void**)&p_h_h,    g_h_h);
    cudaGetSymbolAddress((void**)&p_hf,     g_hf);
    cudaGetSymbolAddress((void**)&p_Wqkv,   g_Wqkv);
    cudaGetSymbolAddress((void**)&p_WoT,    g_WoT);
    cudaGetSymbolAddress((void**)&p_W1T,    g_W1T);
    cudaGetSymbolAddress((void**)&p_W2T,    g_W2T);
    cudaGetSymbolAddress((void**)&p_bqkv,   g_bqkv);

    prep_weights<<<5123, dim3(32, 8)>>>(Wq, Wk, Wv, Wo, W1, W2, bq, bk, bv,
                                        p_Wqkv, p_WoT, p_W1T, p_W2T, p_bqkv);
    ln_kernel<<<NTOK, 256>>>(x, alpha1, beta1, p_xn, p_xn_h);
    hgemm<<<dim3(24, 32), 256>>>(p_xn_h, p_Wqkv, p_bqkv, nullptr,
                                 nullptr, p_qkv, NTOK, 3072, 1024, 0);
    attn<<<dim3(SEQ / 128, NH, 2), 256>>>(p_qkv, p_attn_h);
    hgemm<<<dim3(8, 32), 256>>>(p_attn_h, p_WoT, bo, p_xn,
                                p_x1, nullptr, NTOK, 1024, 1024, 0);
    ln_kernel<<<NTOK, 256>>>(p_x1, alpha2, beta2, nullptr, p_h_h);
    hgemm<<<dim3(4, 32), 256>>>(p_h_h, p_W1T, b1, nullptr,
                                nullptr, p_hf, NTOK, 512, 1024, 1);
    hgemm<<<dim3(8, 32), 256>>>(p_hf, p_W2T, b2, p_x1,
                                out, nullptr, NTOK, 1024, 512, 0);
}

// round 17
// speedup vs baseline: 1.0742x; 1.0141x over previous
#include <cuda_runtime.h>
#include <cuda_fp16.h>
#include <math.h>

#define NTOK 4096
#define DMODEL 1024
#define DFF 512
#define NH 16
#define DH 64
#define SEQ 2048

// ---------------- scratch (device globals: alloc-free, capture-safe) -------
__device__ float  g_xn[NTOK * DMODEL];
__device__ __half g_xn_h[NTOK * DMODEL];
__device__ __half g_qkv[NTOK * 3 * DMODEL];
__device__ __half g_attn_h[NTOK * DMODEL];
__device__ float  g_x1[NTOK * DMODEL];
__device__ __half g_h_h[NTOK * DMODEL];
__device__ __half g_hf[NTOK * DFF];
__device__ __half g_Wqkv[3 * DMODEL * DMODEL];
__device__ __half g_WoT[DMODEL * DMODEL];
__device__ __half g_W1T[DFF * DMODEL];
__device__ __half g_W2T[DMODEL * DFF];
__device__ float  g_bqkv[3 * DMODEL];

// ---------------- PTX helpers ---------------------------------------------
__device__ __forceinline__ unsigned sptr(const void* p) {
    return (unsigned)__cvta_generic_to_shared(p);
}
__device__ __forceinline__ void ldsm4(unsigned* r, unsigned addr) {
    asm volatile("ldmatrix.sync.aligned.m8n8.x4.shared.b16 {%0,%1,%2,%3}, [%4];"
        : "=r"(r[0]), "=r"(r[1]), "=r"(r[2]), "=r"(r[3]) : "r"(addr));
}
__device__ __forceinline__ void ldsm4t(unsigned* r, unsigned addr) {
    asm volatile("ldmatrix.sync.aligned.m8n8.x4.trans.shared.b16 {%0,%1,%2,%3}, [%4];"
        : "=r"(r[0]), "=r"(r[1]), "=r"(r[2]), "=r"(r[3]) : "r"(addr));
}
__device__ __forceinline__ void mma16816(float* c, const unsigned* a, unsigned b0, unsigned b1) {
    asm volatile("mma.sync.aligned.m16n8k16.row.col.f32.f16.f16.f32 "
        "{%0,%1,%2,%3},{%4,%5,%6,%7},{%8,%9},{%0,%1,%2,%3};"
        : "+f"(c[0]), "+f"(c[1]), "+f"(c[2]), "+f"(c[3])
        : "r"(a[0]), "r"(a[1]), "r"(a[2]), "r"(a[3]), "r"(b0), "r"(b1));
}
__device__ __forceinline__ void cpa16(unsigned dst, const void* src) {
    asm volatile("cp.async.cg.shared.global [%0], [%1], 16;" :: "r"(dst), "l"(src));
}
__device__ __forceinline__ void cp_commit() { asm volatile("cp.async.commit_group;"); }
__device__ __forceinline__ void cp_wait0()  { asm volatile("cp.async.wait_group 0;"); }

// ---------------- fused weight prep: transpose + fp32->half + bias --------
__global__ void prep_weights(const float* __restrict__ Wq, const float* __restrict__ Wk,
                             const float* __restrict__ Wv, const float* __restrict__ Wo,
                             const float* __restrict__ W1, const float* __restrict__ W2,
                             const float* __restrict__ bq, const float* __restrict__ bk,
                             const float* __restrict__ bv,
                             __half* __restrict__ Wqkv, __half* __restrict__ WoT,
                             __half* __restrict__ W1T, __half* __restrict__ W2T,
                             float* __restrict__ bqkv) {
    int id = blockIdx.x;
    int tx = threadIdx.x, ty = threadIdx.y;
    if (id >= 5120) {
        int w = id - 5120;
        const float* s = (w == 0) ? bq : (w == 1) ? bk : bv;
        int i = ty * 32 + tx;
#pragma unroll
        for (int j = 0; j < 4; j++) bqkv[w * 1024 + i + j * 256] = s[i + j * 256];
        return;
    }
    const float* src; __half* dst; int K, N, tile;
    if (id < 3072) {
        int w = id >> 10; tile = id & 1023;
        src = (w == 0) ? Wq : (w == 1) ? Wk : Wv;
        dst = Wqkv + (size_t)w * 1024 * 1024; K = 1024; N = 1024;
    } else if (id < 4096) { tile = id - 3072; src = Wo; dst = WoT; K = 1024; N = 1024; }
    else if (id < 4608)   { tile = id - 4096; src = W1; dst = W1T; K = 1024; N = 512; }
    else                  { tile = id - 4608; src = W2; dst = W2T; K = 512;  N = 1024; }
    int ntx = N >> 5;
    int k0 = (tile / ntx) * 32, n0 = (tile % ntx) * 32;
    __shared__ float t2[32][33];
#pragma unroll
    for (int i = 0; i < 4; i++)
        t2[ty + i * 8][tx] = src[(size_t)(k0 + ty + i * 8) * N + n0 + tx];
    __syncthreads();
#pragma unroll
    for (int i = 0; i < 4; i++)
        dst[(size_t)(n0 + ty + i * 8) * K + k0 + tx] = __float2half_rn(t2[tx][ty + i * 8]);
}

// ---------------- LayerNorm (unbiased var), fp32 + half outputs -----------
__global__ void ln_kernel(const float* __restrict__ x,
                          const float* __restrict__ alpha,
                          const float* __restrict__ beta,
                          float* __restrict__ y, __half* __restrict__ yh) {
    int row = blockIdx.x;
    int t = threadIdx.x;
    const float4* xr = (const float4*)(x + (size_t)row * DMODEL);
    float4 v = xr[t];
    float s  = v.x + v.y + v.z + v.w;
    float ss = v.x * v.x + v.y * v.y + v.z * v.z + v.w * v.w;
    __shared__ float sbuf[8], sbuf2[8];
#pragma unroll
    for (int m = 16; m; m >>= 1) {
        s  += __shfl_xor_sync(0xffffffffu, s, m);
        ss += __shfl_xor_sync(0xffffffffu, ss, m);
    }
    if ((t & 31) == 0) { sbuf[t >> 5] = s; sbuf2[t >> 5] = ss; }
    __syncthreads();
    if (t < 32) {
        s  = (t < 8) ? sbuf[t]  : 0.0f;
        ss = (t < 8) ? sbuf2[t] : 0.0f;
#pragma unroll
        for (int m = 4; m; m >>= 1) {
            s  += __shfl_xor_sync(0xffffffffu, s, m);
            ss += __shfl_xor_sync(0xffffffffu, ss, m);
        }
        if (t == 0) { sbuf[0] = s; sbuf2[0] = ss; }
    }
    __syncthreads();
    s = sbuf[0]; ss = sbuf2[0];
    float mean = s * (1.0f / DMODEL);
    float var  = (ss - (float)DMODEL * mean * mean) * (1.0f / (DMODEL - 1));
    float rstd = rsqrtf(var + 1e-6f);
    float4 a = ((const float4*)alpha)[t];
    float4 b = ((const float4*)beta)[t];
    float4 o;
    o.x = a.x * (v.x - mean) * rstd + b.x;
    o.y = a.y * (v.y - mean) * rstd + b.y;
    o.z = a.z * (v.z - mean) * rstd + b.z;
    o.w = a.w * (v.w - mean) * rstd + b.w;
    if (y) ((float4*)(y + (size_t)row * DMODEL))[t] = o;
    if (yh) {
        __half* p = yh + (size_t)row * DMODEL + t * 4;
        *(__half2*)(p)     = __floats2half2_rn(o.x, o.y);
        *(__half2*)(p + 2) = __floats2half2_rn(o.z, o.w);
    }
}

// ---------------- tensor-core GEMM, cp.async 2-stage pipeline (R4 best) ---
#define GP 40
__global__ __launch_bounds__(256) void hgemm(
    const __half* __restrict__ A, const __half* __restrict__ B,
    const float* __restrict__ bias, const float* __restrict__ res,
    float* __restrict__ Cf, __half* __restrict__ Ch,
    int M, int N, int K, int relu) {
    __shared__ __half As[2][128 * GP];
    __shared__ __half Bs[2][128 * GP];
    int t = threadIdx.x, lane = t & 31, warp = t >> 5;
    int wy = warp >> 2, wx = warp & 3;
    int bm = blockIdx.y * 128, bn = blockIdx.x * 128;

    float acc[4][4][4];
#pragma unroll
    for (int i = 0; i < 4; i++)
#pragma unroll
        for (int j = 0; j < 4; j++)
#pragma unroll
            for (int c = 0; c < 4; c++) acc[i][j][c] = 0.0f;

    const __half* Ag = A + (size_t)(bm + (t >> 1)) * K + (t & 1) * 16;
    const __half* Bg = B + (size_t)(bn + (t >> 1)) * K + (t & 1) * 16;
    unsigned ldoff = ((t >> 1) * GP + (t & 1) * 16) * 2;
    unsigned asb[2] = {sptr(As[0]), sptr(As[1])};
    unsigned bsb[2] = {sptr(Bs[0]), sptr(Bs[1])};

    int arow = ((lane >> 3) & 1) * 8 + (lane & 7);
    int acol = (lane >> 4) * 8;
    int brow = (lane >> 4) * 8 + (lane & 7);
    int bcol = ((lane >> 3) & 1) * 8;

    {
        cpa16(asb[0] + ldoff, Ag);      cpa16(asb[0] + ldoff + 16, Ag + 8);
        cpa16(bsb[0] + ldoff, Bg);      cpa16(bsb[0] + ldoff + 16, Bg + 8);
        cp_commit();
    }
    int nIter = K >> 5;
    for (int it = 0; it < nIter; it++) {
        cp_wait0();
        __syncthreads();
        if (it + 1 < nIter) {
            int st = (it + 1) & 1, k0 = (it + 1) << 5;
            cpa16(asb[st] + ldoff, Ag + k0);      cpa16(asb[st] + ldoff + 16, Ag + k0 + 8);
            cpa16(bsb[st] + ldoff, Bg + k0);      cpa16(bsb[st] + ldoff + 16, Bg + k0 + 8);
            cp_commit();
        }
        unsigned as_u = asb[it & 1], bs_u = bsb[it & 1];
#pragma unroll
        for (int ks = 0; ks < 2; ks++) {
            unsigned af[4][4], bf[2][4];
#pragma unroll
            for (int mi = 0; mi < 4; mi++)
                ldsm4(af[mi], as_u + 2u * ((wy * 64 + mi * 16 + arow) * GP + ks * 16 + acol));
#pragma unroll
            for (int g = 0; g < 2; g++)
                ldsm4(bf[g], bs_u + 2u * ((wx * 32 + g * 16 + brow) * GP + ks * 16 + bcol));
#pragma unroll
            for (int mi = 0; mi < 4; mi++)
#pragma unroll
                for (int ni = 0; ni < 4; ni++)
                    mma16816(acc[mi][ni], af[mi], bf[ni >> 1][(ni & 1) * 2], bf[ni >> 1][(ni & 1) * 2 + 1]);
        }
    }

#pragma unroll
    for (int mi = 0; mi < 4; mi++) {
        int r = bm + wy * 64 + mi * 16 + (lane >> 2);
#pragma unroll
        for (int ni = 0; ni < 4; ni++) {
            int c = bn + wx * 32 + ni * 8 + 2 * (lane & 3);
            float* a = acc[mi][ni];
            float2 bb = *(const float2*)(bias + c);
            float v0 = a[0] + bb.x, v1 = a[1] + bb.y;
            float v2 = a[2] + bb.x, v3 = a[3] + bb.y;
            if (res) {
                float2 r0 = *(const float2*)(res + (size_t)r * N + c);
                float2 r1 = *(const float2*)(res + (size_t)(r + 8) * N + c);
                v0 += r0.x; v1 += r0.y; v2 += r1.x; v3 += r1.y;
            }
            if (relu) {
                v0 = fmaxf(v0, 0.0f); v1 = fmaxf(v1, 0.0f);
                v2 = fmaxf(v2, 0.0f); v3 = fmaxf(v3, 0.0f);
            }
            if (Cf) {
                *(float2*)(Cf + (size_t)r * N + c)       = make_float2(v0, v1);
                *(float2*)(Cf + (size_t)(r + 8) * N + c) = make_float2(v2, v3);
            }
            if (Ch) {
                *(__half2*)(Ch + (size_t)r * N + c)       = __floats2half2_rn(v0, v1);
                *(__half2*)(Ch + (size_t)(r + 8) * N + c) = __floats2half2_rn(v2, v3);
            }
        }
    }
}

// ---------------- flash attention: exp2 softmax via h2exp2 (f16x2 MUFU) ---
// 256 thr / 128 q-rows. Q pre-scaled by log2(e)/8; P computed directly in
// half precision (it is quantized to half for the PV mma regardless).
#define AP 72
#define QSCALE 0.18033688011112042f   // log2(e)/8
__global__ __launch_bounds__(256) void attn(const __half* __restrict__ qkv,
                                            __half* __restrict__ o) {
    __shared__ __half smA[128 * AP];   // Q staging, then K/V stage 1
    __shared__ __half smB[128 * AP];   // K/V stage 0
    int t = threadIdx.x, lane = t & 31, warp = t >> 5;
    int qt = blockIdx.x, h = blockIdx.y, b = blockIdx.z;
    size_t tq0 = (size_t)b * SEQ + qt * 128;
    const __half* Qg = qkv + tq0 * 3072 + h * 64;
    const __half* Kg = qkv + ((size_t)b * SEQ) * 3072 + 1024 + h * 64;
    const __half* Vg = Kg + 1024;

    unsigned ksu[2] = {sptr(smB), sptr(smA)};
    unsigned vsu[2] = {sptr(smB + 64 * AP), sptr(smA + 64 * AP)};

    int ldrow = t >> 2, ldo = (t & 3) * 16;
    unsigned kvoff = (ldrow * AP + ldo) * 2;

    // prologue: K/V tile 0 -> stage 0 (region B); overlaps Q staging
    {
        size_t tb = (size_t)ldrow * 3072;
        cpa16(ksu[0] + kvoff, Kg + tb + ldo);      cpa16(ksu[0] + kvoff + 16, Kg + tb + ldo + 8);
        cpa16(vsu[0] + kvoff, Vg + tb + ldo);      cpa16(vsu[0] + kvoff + 16, Vg + tb + ldo + 8);
        cp_commit();
    }

    // stage Q (128 x 64 halves) into region A, pre-scaled by log2(e)/8
    {
        int row = t >> 1;
        const __half* src = Qg + (size_t)row * 3072 + (t & 1) * 32;
        __half* dst = smA + row * AP + (t & 1) * 32;
        __half2 qs = __float2half2_rn(QSCALE);
#pragma unroll
        for (int i = 0; i < 16; i++) {
            __half2 qv = *(const __half2*)(src + i * 2);
            *(__half2*)(dst + i * 2) = __hmul2(qv, qs);
        }
    }
    __syncthreads();

    int arow = ((lane >> 3) & 1) * 8 + (lane & 7);
    int acol = (lane >> 4) * 8;
    unsigned smA_u = sptr(smA);
    unsigned qf[4][4];
#pragma unroll
    for (int ks = 0; ks < 4; ks++)
        ldsm4(qf[ks], smA_u + 2u * ((warp * 16 + arow) * AP + ks * 16 + acol));

    float m0 = -1e30f, m1 = -1e30f, l0 = 0.0f, l1 = 0.0f;
    float O[8][4];
#pragma unroll
    for (int j = 0; j < 8; j++)
#pragma unroll
        for (int c = 0; c < 4; c++) O[j][c] = 0.0f;

    int krow = (lane >> 4) * 8 + (lane & 7);
    int kcol = ((lane >> 3) & 1) * 8;
    int vrow = ((lane >> 3) & 1) * 8 + (lane & 7);
    int vcol = (lane >> 4) * 8;

    for (int kt = 0; kt < 32; kt++) {
        cp_wait0();
        __syncthreads();
        if (kt + 1 < 32) {
            int st = (kt + 1) & 1;
            size_t tb = (size_t)((kt + 1) * 64 + ldrow) * 3072;
            cpa16(ksu[st] + kvoff, Kg + tb + ldo);      cpa16(ksu[st] + kvoff + 16, Kg + tb + ldo + 8);
            cpa16(vsu[st] + kvoff, Vg + tb + ldo);      cpa16(vsu[st] + kvoff + 16, Vg + tb + ldo + 8);
            cp_commit();
        }
        unsigned ks_u = ksu[kt & 1], vs_u = vsu[kt & 1];

        // S = Qs @ K^T (log2 domain)
        float s[8][4];
#pragma unroll
        for (int j = 0; j < 8; j++)
#pragma unroll
            for (int c = 0; c < 4; c++) s[j][c] = 0.0f;
#pragma unroll
        for (int ks = 0; ks < 4; ks++) {
            unsigned kf[4][4];
#pragma unroll
            for (int g = 0; g < 4; g++)
                ldsm4(kf[g], ks_u + 2u * ((g * 16 + krow) * AP + ks * 16 + kcol));
#pragma unroll
            for (int j = 0; j < 8; j++)
                mma16816(s[j], qf[ks], kf[j >> 1][(j & 1) * 2], kf[j >> 1][(j & 1) * 2 + 1]);
        }

        // online softmax: exp2 in f16x2 (1 MUFU per 2 elements)
        float mx0 = -1e30f, mx1 = -1e30f;
#pragma unroll
        for (int j = 0; j < 8; j++) {
            mx0 = fmaxf(mx0, fmaxf(s[j][0], s[j][1]));
            mx1 = fmaxf(mx1, fmaxf(s[j][2], s[j][3]));
        }
        mx0 = fmaxf(mx0, __shfl_xor_sync(0xffffffffu, mx0, 1));
        mx0 = fmaxf(mx0, __shfl_xor_sync(0xffffffffu, mx0, 2));
        mx1 = fmaxf(mx1, __shfl_xor_sync(0xffffffffu, mx1, 1));
        mx1 = fmaxf(mx1, __shfl_xor_sync(0xffffffffu, mx1, 2));
        bool up0 = mx0 > m0, up1 = mx1 > m1;
        float mn0 = up0 ? mx0 : m0, mn1 = up1 ? mx1 : m1;
        if (up0 | up1) {
            float al0 = up0 ? exp2f(m0 - mn0) : 1.0f;
            float al1 = up1 ? exp2f(m1 - mn1) : 1.0f;
            m0 = mn0; m1 = mn1;
            l0 *= al0; l1 *= al1;
#pragma unroll
            for (int j = 0; j < 8; j++) {
                O[j][0] *= al0; O[j][1] *= al0;
                O[j][2] *= al1; O[j][3] *= al1;
            }
        }
        float sum0 = 0.0f, sum1 = 0.0f;
        unsigned pa[8], pb[8];
#pragma unroll
        for (int j = 0; j < 8; j++) {
            __half2 d0 = __floats2half2_rn(s[j][0] - mn0, s[j][1] - mn0);
            __half2 d1 = __floats2half2_rn(s[j][2] - mn1, s[j][3] - mn1);
            __half2 e0 = h2exp2(d0);
            __half2 e1 = h2exp2(d1);
            pa[j] = *(unsigned*)&e0;
            pb[j] = *(unsigned*)&e1;
            float2 f0 = __half22float2(e0);
            float2 f1 = __half22float2(e1);
            sum0 += f0.x + f0.y;
            sum1 += f1.x + f1.y;
        }
        sum0 += __shfl_xor_sync(0xffffffffu, sum0, 1);
        sum0 += __shfl_xor_sync(0xffffffffu, sum0, 2);
        sum1 += __shfl_xor_sync(0xffffffffu, sum1, 1);
        sum1 += __shfl_xor_sync(0xffffffffu, sum1, 2);
        l0 += sum0;
        l1 += sum1;

        // O += P @ V
#pragma unroll
        for (int ks = 0; ks < 4; ks++) {
            unsigned vf[4][4];
#pragma unroll
            for (int g = 0; g < 4; g++)
                ldsm4t(vf[g], vs_u + 2u * ((ks * 16 + vrow) * AP + g * 16 + vcol));
            unsigned pfr[4] = {pa[2 * ks], pb[2 * ks], pa[2 * ks + 1], pb[2 * ks + 1]};
#pragma unroll
            for (int j = 0; j < 8; j++)
                mma16816(O[j], pfr, vf[j >> 1][(j & 1) * 2], vf[j >> 1][(j & 1) * 2 + 1]);
        }
    }

    float i0 = 1.0f / l0, i1 = 1.0f / l1;
    __half* ob = o + (tq0 + warp * 16 + (lane >> 2)) * 1024 + h * 64 + 2 * (lane & 3);
#pragma unroll
    for (int j = 0; j < 8; j++) {
        *(__half2*)(ob + j * 8)            = __floats2half2_rn(O[j][0] * i0, O[j][1] * i0);
        *(__half2*)(ob + 8 * 1024 + j * 8) = __floats2half2_rn(O[j][2] * i1, O[j][3] * i1);
    }
}

// ---------------------------------------------------------------------------
extern "C" void kernel_launch(void* const* d_in, const int* in_sizes, int n_in,
                              void* d_out, int out_size) {
    const float* x      = (const float*)d_in[0];
    const float* Wq     = (const float*)d_in[1];
    const float* bq     = (const float*)d_in[2];
    const float* Wk     = (const float*)d_in[3];
    const float* bk     = (const float*)d_in[4];
    const float* Wv     = (const float*)d_in[5];
    const float* bv     = (const float*)d_in[6];
    const float* Wo     = (const float*)d_in[7];
    const float* bo     = (const float*)d_in[8];
    const float* alpha1 = (const float*)d_in[9];
    const float* beta1  = (const float*)d_in[10];
    const float* alpha2 = (const float*)d_in[11];
    const float* beta2  = (const float*)d_in[12];
    const float* W1     = (const float*)d_in[13];
    const float* b1     = (const float*)d_in[14];
    const float* W2     = (const float*)d_in[15];
    const float* b2     = (const float*)d_in[16];
    float* out = (float*)d_out;

    float *p_xn, *p_x1, *p_bqkv;
    __half *p_xn_h, *p_qkv, *p_attn_h, *p_h_h, *p_hf;
    __half *p_Wqkv, *p_WoT, *p_W1T, *p_W2T;
    cudaGetSymbolAddress((void**)&p_xn,     g_xn);
    cudaGetSymbolAddress((void**)&p_xn_h,   g_xn_h);
    cudaGetSymbolAddress((void**)&p_qkv,    g_qkv);
    cudaGetSymbolAddress((void**)&p_attn_h, g_attn_h);
    cudaGetSymbolAddress((void**)&p_x1,     g_x1);
    cudaGetSymbolAddress((void**)&p_h_h,    g_h_h);
    cudaGetSymbolAddress((void**)&p_hf,     g_hf);
    cudaGetSymbolAddress((void**)&p_Wqkv,   g_Wqkv);
    cudaGetSymbolAddress((void**)&p_WoT,    g_WoT);
    cudaGetSymbolAddress((void**)&p_W1T,    g_W1T);
    cudaGetSymbolAddress((void**)&p_W2T,    g_W2T);
    cudaGetSymbolAddress((void**)&p_bqkv,   g_bqkv);

    prep_weights<<<5123, dim3(32, 8)>>>(Wq, Wk, Wv, Wo, W1, W2, bq, bk, bv,
                                        p_Wqkv, p_WoT, p_W1T, p_W2T, p_bqkv);
    ln_kernel<<<NTOK, 256>>>(x, alpha1, beta1, p_xn, p_xn_h);
    hgemm<<<dim3(24, 32), 256>>>(p_xn_h, p_Wqkv, p_bqkv, nullptr,
                                 nullptr, p_qkv, NTOK, 3072, 1024, 0);
    attn<<<dim3(SEQ / 128, NH, 2), 256>>>(p_qkv, p_attn_h);
    hgemm<<<dim3(8, 32), 256>>>(p_attn_h, p_WoT, bo, p_xn,
                                p_x1, nullptr, NTOK, 1024, 1024, 0);
    ln_kernel<<<NTOK, 256>>>(p_x1, alpha2, beta2, nullptr, p_h_h);
    hgemm<<<dim3(4, 32), 256>>>(p_h_h, p_W1T, b1, nullptr,
                                nullptr, p_hf, NTOK, 512, 1024, 1);
    hgemm<<<dim3(8, 32), 256>>>(p_hf, p_W2T, b2, p_x1,
                                out, nullptr, NTOK, 1024, 512, 0);
}